// round 5
// baseline (speedup 1.0000x reference)
#include <cuda_runtime.h>

// Shape: a, b, h : (B=2, S=2048, D=1024, N=16) fp32, row-major.
// h[t] = a[t]*h[t-1] + b[t] along S. B*D*N = 32768 independent channels,
// contiguous at fixed t; scan stride = D*N = 16384 floats.
//
// R4: U=8 timesteps/group, prefetch distance 4, 8-buffer register ring.
// Keeps ~50-55 warp-LDGs outstanding continuously (vs ~27 time-averaged in
// R3's U=16/dist-2), pinning the per-warp outstanding-load cap through the
// short consume phases -> chip-wide in-flight ~7 MB > ~3.6 MB BW*latency
// product -> DRAM-bandwidth-bound.

static constexpr int S_LEN   = 2048;
static constexpr int STRIDE  = 1024 * 16;       // D*N floats between timesteps
static constexpr int CHANNELS = 2 * STRIDE;     // 32768
static constexpr int U       = 8;               // timesteps per group
static constexpr int N_GROUPS = S_LEN / U;      // 256
static constexpr int N_SUPER  = N_GROUPS / 8;   // 32 super-iterations (8 groups each)

// Load local group G (relative to current ap/bp) into buffers A/B.
#define PREF(A, B, G)                                            \
    _Pragma("unroll")                                            \
    for (int u = 0; u < U; u++) {                                \
        A[u] = __ldcs(ap + ((G) * U + u) * STRIDE);              \
        B[u] = __ldcs(bp + ((G) * U + u) * STRIDE);              \
    }

// Consume buffers A/B as local group G: serial FMA chain + streaming stores.
#define CONS(A, B, G)                                            \
    _Pragma("unroll")                                            \
    for (int u = 0; u < U; u++) {                                \
        h = fmaf(A[u], h, B[u]);                                 \
        __stcs(op + ((G) * U + u) * STRIDE, h);                  \
    }

__global__ __launch_bounds__(256, 1)
void ParallelScan_37374805409922_kernel(const float* __restrict__ a,
                                        const float* __restrict__ b,
                                        float* __restrict__ out) {
    const int idx   = blockIdx.x * blockDim.x + threadIdx.x;  // 0..32767
    const int batch = idx >> 14;                               // / 16384
    const int col   = idx & (STRIDE - 1);
    const size_t base = (size_t)batch * S_LEN * STRIDE + col;

    const float* __restrict__ ap = a + base;
    const float* __restrict__ bp = b + base;
    float* __restrict__ op = out + base;

    float a0[U], b0[U], a1[U], b1[U], a2[U], b2[U], a3[U], b3[U];
    float a4[U], b4[U], a5[U], b5[U], a6[U], b6[U], a7[U], b7[U];
    float h = 0.0f;

    // Prologue: 4 groups in flight before any consumption.
    PREF(a0, b0, 0)
    PREF(a1, b1, 1)
    PREF(a2, b2, 2)
    PREF(a3, b3, 3)

    #pragma unroll 1
    for (int s = 0; s < N_SUPER; s++) {
        // Steady state: issue one group of loads, consume one group — always
        // 4 groups of loads ahead of the consume point.
        PREF(a4, b4, 4)  CONS(a0, b0, 0)
        PREF(a5, b5, 5)  CONS(a1, b1, 1)
        PREF(a6, b6, 6)  CONS(a2, b2, 2)
        PREF(a7, b7, 7)  CONS(a3, b3, 3)

        if (s + 1 < N_SUPER) {
            PREF(a0, b0, 8)   CONS(a4, b4, 4)
            PREF(a1, b1, 9)   CONS(a5, b5, 5)
            PREF(a2, b2, 10)  CONS(a6, b6, 6)
            PREF(a3, b3, 11)  CONS(a7, b7, 7)
        } else {
            CONS(a4, b4, 4)
            CONS(a5, b5, 5)
            CONS(a6, b6, 6)
            CONS(a7, b7, 7)
        }

        ap += 8 * U * STRIDE;
        bp += 8 * U * STRIDE;
        op += 8 * U * STRIDE;
    }
}

extern "C" void kernel_launch(void* const* d_in, const int* in_sizes, int n_in,
                              void* d_out, int out_size) {
    const float* a = (const float*)d_in[0];
    const float* b = (const float*)d_in[1];
    float* out = (float*)d_out;
    (void)in_sizes; (void)n_in; (void)out_size;

    ParallelScan_37374805409922_kernel<<<CHANNELS / 256, 256>>>(a, b, out);
}